// round 13
// baseline (speedup 1.0000x reference)
#include <cuda_runtime.h>

// EnergyModel: energy[t] = sum_q qa[q] * sum_f w[f]*(desc[t,q,f]-qf[t,q,f])^2
// with range masking on T[:,4:7]. HBM-bound streaming reduction.
//
// R13: R12's single-kernel structure (in-producer last-CTA-per-row fold,
// which removed R8's 2.8us finalize exposure) + a compiler scheduling
// barrier (asm memory clobber) between the load batch and the consume
// phase. R10/R11/R12 all showed ptxas re-balancing registers (46 -> ~39)
// and interleaving load/consume, collapsing MLP 6 -> ~2 and the rate
// 5.9 -> 5.06 TB/s. The barrier makes the 6-deep LDG.128 batch
// codegen-drift-proof.

#define NQ 128
#define FDIM 576                    // 64*1 + 64*3 + 64*5
#define NGRP 192
#define SPLIT 8
#define QPC (NQ / SPLIT)            // 16 queries per chunk
#define THREADS 256
#define F4_PER_ROW (FDIM / 4)       // 144
#define F4_TOTAL (NQ * F4_PER_ROW)  // 18432 float4 per t per tensor
#define CHUNK_F4 (QPC * F4_PER_ROW) // 2304 float4 per chunk per tensor
#define NT_MAX 1024
#define NBATCH 3
#define UB 3                        // float4-pairs batched per phase (MLP=6)

__device__ float g_partial[NT_MAX * SPLIT];
__device__ int   g_count[NT_MAX];    // zero-init; folding CTA resets to 0

__global__ void __launch_bounds__(THREADS)
energy_kernel(const float* __restrict__ T,
              const float4* __restrict__ desc,
              const float4* __restrict__ qf,
              const float* __restrict__ qa,
              const float* __restrict__ logit,
              const float* __restrict__ ranges,
              float* __restrict__ out)
{
    const int bx  = blockIdx.x;
    const int t   = bx >> 3;             // SPLIT == 8
    const int c   = bx & (SPLIT - 1);
    const int tid = threadIdx.x;

    // Range mask: uniform predicate; dead CTAs retire without touching payload.
    {
        const float x0 = T[t * 7 + 4];
        const float x1 = T[t * 7 + 5];
        const float x2 = T[t * 7 + 6];
        const bool ok = (ranges[1] >= x0) && (x0 >= ranges[0]) &&
                        (ranges[3] >= x1) && (x1 >= ranges[2]) &&
                        (ranges[5] >= x2) && (x2 >= ranges[4]);
        if (!ok) {
            if (c == 0 && tid == 0) out[t] = 100000.0f;
            return;
        }
    }

    __shared__ float s_g[NGRP];
    __shared__ float s_w[FDIM];
    __shared__ float s_qa[QPC];
    __shared__ float s_red[THREADS / 32];

    // Weight setup: 192 softplus -> expand to 576 per-feature weights (LDS only).
    const float scale = 2.0f / (0.6931471805599453f * (float)NGRP);
    if (tid < NGRP) {
        const float x = logit[tid];
        s_g[tid] = (fmaxf(x, 0.0f) + log1pf(expf(-fabsf(x)))) * scale;
    }
    if (tid < QPC) s_qa[tid] = qa[c * QPC + tid];
    __syncthreads();
    for (int f = tid; f < FDIM; f += THREADS) {
        int g;
        if (f < 64)        g = f;                    // l=0, d=1
        else if (f < 256)  g = 64 + (f - 64) / 3;    // l=1, d=3
        else               g = 128 + (f - 256) / 5;  // l=2, d=5
        s_w[f] = s_g[g];
    }
    __syncthreads();

    const float4* db = desc + (size_t)t * F4_TOTAL + (size_t)c * CHUNK_F4;
    const float4* qb = qf   + (size_t)t * F4_TOTAL + (size_t)c * CHUNK_F4;
    const float4* s_w4 = (const float4*)s_w;

    float acc = 0.0f;
    #pragma unroll
    for (int b = 0; b < NBATCH; b++) {
        float4 dv[UB], ev[UB];
        // Phase 1: issue all 6 independent loads (MLP_p1 = 6).
        #pragma unroll
        for (int u = 0; u < UB; u++) {
            const int j = tid + (b * UB + u) * THREADS;
            dv[u] = db[j];
            ev[u] = qb[j];
        }
        // Scheduling fence: ptxas may not sink the loads above past this
        // point — guarantees all 6 LDG.128 issue before any consume.
        asm volatile("" ::: "memory");
        // Phase 2: consume.
        #pragma unroll
        for (int u = 0; u < UB; u++) {
            const int j  = tid + (b * UB + u) * THREADS;
            const int q  = j / F4_PER_ROW;
            const int f4 = j - q * F4_PER_ROW;
            const float4 w = s_w4[f4];
            const float dx = dv[u].x - ev[u].x;
            const float dy = dv[u].y - ev[u].y;
            const float dz = dv[u].z - ev[u].z;
            const float dw = dv[u].w - ev[u].w;
            float s = w.x * dx * dx;
            s = fmaf(w.y, dy * dy, s);
            s = fmaf(w.z, dz * dz, s);
            s = fmaf(w.w, dw * dw, s);
            acc = fmaf(s_qa[q], s, acc);
        }
    }

    // Block reduction (8 warps).
    #pragma unroll
    for (int o = 16; o > 0; o >>= 1)
        acc += __shfl_down_sync(0xffffffffu, acc, o);
    if ((tid & 31) == 0) s_red[tid >> 5] = acc;
    __syncthreads();

    if (tid == 0) {
        float v = 0.0f;
        #pragma unroll
        for (int w = 0; w < THREADS / 32; w++) v += s_red[w];
        g_partial[bx] = v;                 // publish partial...
        __threadfence();                   // ...release...
        const int prev = atomicAdd(&g_count[t], 1);
        if (prev == SPLIT - 1) {           // 8th arriver folds this row
            __threadfence();               // acquire peer partials
            const float4 a = __ldcg((const float4*)&g_partial[t * SPLIT]);
            const float4 b = __ldcg((const float4*)&g_partial[t * SPLIT + 4]);
            out[t] = ((a.x + a.y) + (a.z + a.w)) +
                     ((b.x + b.y) + (b.z + b.w));
            g_count[t] = 0;                // reset for next graph replay
        }
    }
}

extern "C" void kernel_launch(void* const* d_in, const int* in_sizes, int n_in,
                              void* d_out, int out_size)
{
    const float*  T      = (const float*)d_in[0];
    const float4* desc   = (const float4*)d_in[1];
    const float4* qf     = (const float4*)d_in[2];
    const float*  qa     = (const float*)d_in[3];
    const float*  logit  = (const float*)d_in[4];
    const float*  ranges = (const float*)d_in[5];
    float* out = (float*)d_out;

    const int nt = in_sizes[0] / 7;   // 1024

    energy_kernel<<<nt * SPLIT, THREADS>>>(T, desc, qf, qa, logit, ranges, out);
}